// round 2
// baseline (speedup 1.0000x reference)
#include <cuda_runtime.h>
#include <stdint.h>

#define COLS 16384
#define TPB  512
#define V4   (COLS / (TPB * 4))   // 8 float4 per thread
#define NW   (TPB / 32)           // 16 warps
#define EQ_CAP 128

struct __align__(16) SmemT {
    unsigned row[COLS];        // 65536 B : raw fp32 bits of the row
    unsigned hist[NW][256];    // 16384 B : per-warp histograms
    unsigned tot[256];         //  1024 B : merged histogram
    int      eqIdx[EQ_CAP];    //   512 B : indices equal to threshold
    unsigned prefix;           // selected key prefix (threshold bits)
    int      r;                // remaining rank
    int      eqCount;
    int      cutoff;           // max index kept among equals
};

// Race-free per-warp histogram add via warp match aggregation.
// d >= 256 is a "not a candidate" sentinel (still participates in match).
__device__ __forceinline__ void hist_add(unsigned* h, unsigned d) {
    unsigned mm = __match_any_sync(0xffffffffu, d);
    if (d < 256u) {
        unsigned leader = __ffs(mm) - 1u;
        if ((threadIdx.x & 31u) == leader) h[d] += (unsigned)__popc(mm);
    }
}

// Warp 0: find largest digit d with suffix_count(d) >= r; update prefix and r.
__device__ __forceinline__ void select_bin(SmemT* s, int shift) {
    const int lane = threadIdx.x & 31;
    const unsigned r = (unsigned)s->r;
    const unsigned base = (unsigned)lane * 8u;
    unsigned loc[8];
    unsigned sum = 0;
#pragma unroll
    for (int j = 7; j >= 0; j--) { sum += s->tot[base + j]; loc[j] = sum; }
    const unsigned lanesum = sum;
    unsigned acc = lanesum;           // inclusive suffix-scan across lanes
#pragma unroll
    for (int o = 1; o < 32; o <<= 1) {
        unsigned v = __shfl_down_sync(0xffffffffu, acc, o);
        if (lane < 32 - o) acc += v;
    }
    const unsigned above = acc - lanesum;   // count in digits > this lane's block
#pragma unroll
    for (int j = 0; j < 8; j++) {
        unsigned g     = above + loc[j];                        // suffix at digit base+j
        unsigned gnext = (j == 7) ? above : (above + loc[j+1]); // suffix at digit base+j+1
        if (g >= r && gnext < r) {          // exactly one (lane,j) satisfies this
            s->prefix |= (base + (unsigned)j) << shift;
            s->r = (int)(r - gnext);
        }
    }
}

__global__ void __launch_bounds__(TPB, 2)
topk_kernel(const float* __restrict__ x, const int* __restrict__ kptr,
            float* __restrict__ out)
{
    extern __shared__ unsigned char smem_raw[];
    SmemT* s = reinterpret_cast<SmemT*>(smem_raw);
    const int tid = threadIdx.x;
    const int w   = tid >> 5;
    const size_t rowoff = (size_t)blockIdx.x * COLS;
    const float4* __restrict__ xin  = reinterpret_cast<const float4*>(x + rowoff);
    float4* __restrict__       xout = reinterpret_cast<float4*>(out + rowoff);

    const int k = *kptr;
    if (k >= COLS) {   // keep everything
#pragma unroll
        for (int i = 0; i < V4; i++) xout[i*TPB + tid] = xin[i*TPB + tid];
        return;
    }
    if (k <= 0) {      // keep nothing
        float4 z = make_float4(0.f, 0.f, 0.f, 0.f);
#pragma unroll
        for (int i = 0; i < V4; i++) xout[i*TPB + tid] = z;
        return;
    }

    // ---- init ----
    unsigned* hflat = &s->hist[0][0];
    for (int i = tid; i < NW * 256; i += TPB) hflat[i] = 0u;
    if (tid == 0) { s->prefix = 0u; s->r = k; s->eqCount = 0; }
    __syncthreads();

    // ---- load gmem -> smem, fused with level-0 histogram (digit = key >> 23) ----
    unsigned* hw = s->hist[w];
#pragma unroll
    for (int i = 0; i < V4; i++) {
        const int i4 = i * TPB + tid;
        float4 v = xin[i4];
        reinterpret_cast<float4*>(s->row)[i4] = v;
        unsigned k0 = __float_as_uint(v.x) & 0x7fffffffu;
        unsigned k1 = __float_as_uint(v.y) & 0x7fffffffu;
        unsigned k2 = __float_as_uint(v.z) & 0x7fffffffu;
        unsigned k3 = __float_as_uint(v.w) & 0x7fffffffu;
        hist_add(hw, k0 >> 23);
        hist_add(hw, k1 >> 23);
        hist_add(hw, k2 >> 23);
        hist_add(hw, k3 >> 23);
    }
    __syncthreads();

    // ---- 4-level radix select over the 31-bit key, split 8+8+8+7 (no overlap) ----
#pragma unroll
    for (int lev = 0; lev < 4; lev++) {
        // per-level bit geometry
        const int      shift = (lev == 0) ? 23 : (lev == 1) ? 15 : (lev == 2) ? 7 : 0;
        const int      hi    = (lev == 1) ? 23 : (lev == 2) ? 15 : 7;   // lev>0 only
        const unsigned mask  = (lev == 3) ? 0x7fu : 0xffu;
        if (lev > 0) {
            const unsigned pref_hi = s->prefix >> hi;
#pragma unroll
            for (int i = 0; i < V4; i++) {
                const float4 v = reinterpret_cast<const float4*>(s->row)[i * TPB + tid];
                unsigned kk[4];
                kk[0] = __float_as_uint(v.x) & 0x7fffffffu;
                kk[1] = __float_as_uint(v.y) & 0x7fffffffu;
                kk[2] = __float_as_uint(v.z) & 0x7fffffffu;
                kk[3] = __float_as_uint(v.w) & 0x7fffffffu;
#pragma unroll
                for (int j = 0; j < 4; j++) {
                    unsigned key = kk[j];
                    unsigned d = ((key >> hi) == pref_hi) ? ((key >> shift) & mask)
                                                          : 0x100u;
                    hist_add(hw, d);
                }
            }
            __syncthreads();
        }
        // merge per-warp histograms
        if (tid < 256) {
            unsigned t = 0;
#pragma unroll
            for (int ww = 0; ww < NW; ww++) t += s->hist[ww][tid];
            s->tot[tid] = t;
        }
        __syncthreads();
        if (tid < 32) select_bin(s, shift);
        __syncthreads();
        if (lev < 3) {
            for (int i = tid; i < NW * 256; i += TPB) hflat[i] = 0u;
            __syncthreads();
        }
    }

    const unsigned thr = s->prefix;   // exact bit pattern of |x| at rank boundary
    // s->r = number of elements equal to thr that must still be kept (>=1)

    // ---- collect indices equal to threshold (exact lowest-index tie-break) ----
#pragma unroll
    for (int i = 0; i < V4; i++) {
        const int i4 = i * TPB + tid;
        const float4 v = reinterpret_cast<const float4*>(s->row)[i4];
        unsigned kk[4];
        kk[0] = __float_as_uint(v.x) & 0x7fffffffu;
        kk[1] = __float_as_uint(v.y) & 0x7fffffffu;
        kk[2] = __float_as_uint(v.z) & 0x7fffffffu;
        kk[3] = __float_as_uint(v.w) & 0x7fffffffu;
#pragma unroll
        for (int j = 0; j < 4; j++) {
            if (kk[j] == thr) {
                int pos = atomicAdd(&s->eqCount, 1);
                if (pos < EQ_CAP) s->eqIdx[pos] = i4 * 4 + j;
            }
        }
    }
    __syncthreads();
    if (tid == 0) {
        int e = s->eqCount; if (e > EQ_CAP) e = EQ_CAP;
        int m = s->r;       if (m > e) m = e;
        // insertion sort ascending (e is tiny: typically 1-2)
        for (int a = 1; a < e; a++) {
            int v = s->eqIdx[a]; int b = a - 1;
            while (b >= 0 && s->eqIdx[b] > v) { s->eqIdx[b + 1] = s->eqIdx[b]; b--; }
            s->eqIdx[b + 1] = v;
        }
        s->cutoff = (m > 0) ? s->eqIdx[m - 1] : -1;  // keep equals with idx <= cutoff
    }
    __syncthreads();

    // ---- output pass: smem -> gmem ----
    const int cut = s->cutoff;
#pragma unroll
    for (int i = 0; i < V4; i++) {
        const int i4 = i * TPB + tid;
        const float4 v = reinterpret_cast<const float4*>(s->row)[i4];
        unsigned kk[4];
        kk[0] = __float_as_uint(v.x) & 0x7fffffffu;
        kk[1] = __float_as_uint(v.y) & 0x7fffffffu;
        kk[2] = __float_as_uint(v.z) & 0x7fffffffu;
        kk[3] = __float_as_uint(v.w) & 0x7fffffffu;
        const int e0 = i4 * 4;
        float4 o;
        o.x = (kk[0] > thr || (kk[0] == thr && (e0 + 0) <= cut)) ? v.x : 0.f;
        o.y = (kk[1] > thr || (kk[1] == thr && (e0 + 1) <= cut)) ? v.y : 0.f;
        o.z = (kk[2] > thr || (kk[2] == thr && (e0 + 2) <= cut)) ? v.z : 0.f;
        o.w = (kk[3] > thr || (kk[3] == thr && (e0 + 3) <= cut)) ? v.w : 0.f;
        xout[i4] = o;
    }
}

extern "C" void kernel_launch(void* const* d_in, const int* in_sizes, int n_in,
                              void* d_out, int out_size)
{
    const float* x = (const float*)d_in[0];
    const int*   k = (const int*)d_in[1];
    float* out = (float*)d_out;
    const int rows = in_sizes[0] / COLS;

    cudaFuncSetAttribute(topk_kernel,
                         cudaFuncAttributeMaxDynamicSharedMemorySize,
                         (int)sizeof(SmemT));
    topk_kernel<<<rows, TPB, sizeof(SmemT)>>>(x, k, out);
}

// round 5
// speedup vs baseline: 1.0609x; 1.0609x over previous
#include <cuda_runtime.h>
#include <stdint.h>

#define COLS 16384
#define TPB  512
#define V4   (COLS / (TPB * 4))   // 8 float4 per thread
#define NW   (TPB / 32)           // 16 warps
#define CAP  2048                 // candidate list capacity
#define EQ_CAP 128

struct __align__(16) SmemT {
    unsigned row[COLS];            // 64 KB : raw fp32 bits of the row
    union {
        unsigned           hist[NW][256];   // 16 KB : per-warp hists (level 0 only)
        unsigned long long cand[CAP];       // 16 KB : (key<<32)|idx candidates
    } u;
    unsigned tot[256];             // 1 KB : merged / refinement histogram
    int      eqIdx[EQ_CAP];
    unsigned prefix;
    int      r;
    int      eqCount;
    int      candCount;
    int      cutoff;
};

// Race-free per-warp histogram add (non-atomic; one warp owns h).
__device__ __forceinline__ void hist_add(unsigned* h, unsigned d) {
    unsigned mm = __match_any_sync(0xffffffffu, d);
    if (d < 256u) {
        unsigned leader = __ffs(mm) - 1u;
        if ((threadIdx.x & 31u) == leader) h[d] += (unsigned)__popc(mm);
    }
}

// Shared histogram add with warp aggregation (multiple warps may target h).
__device__ __forceinline__ void hist_add_atomic(unsigned* h, unsigned d) {
    unsigned mm = __match_any_sync(0xffffffffu, d);
    if (d < 256u) {
        unsigned leader = __ffs(mm) - 1u;
        if ((threadIdx.x & 31u) == leader) atomicAdd(&h[d], (unsigned)__popc(mm));
    }
}

// Warp 0: find largest digit d with suffix_count(d) >= r; update prefix and r.
__device__ __forceinline__ void select_bin(SmemT* s, int shift) {
    const int lane = threadIdx.x & 31;
    const unsigned r = (unsigned)s->r;
    const unsigned base = (unsigned)lane * 8u;
    unsigned loc[8];
    unsigned sum = 0;
#pragma unroll
    for (int j = 7; j >= 0; j--) { sum += s->tot[base + j]; loc[j] = sum; }
    const unsigned lanesum = sum;
    unsigned acc = lanesum;           // inclusive suffix-scan across lanes
#pragma unroll
    for (int o = 1; o < 32; o <<= 1) {
        unsigned v = __shfl_down_sync(0xffffffffu, acc, o);
        if (lane < 32 - o) acc += v;
    }
    const unsigned above = acc - lanesum;
#pragma unroll
    for (int j = 0; j < 8; j++) {
        unsigned g     = above + loc[j];
        unsigned gnext = (j == 7) ? above : (above + loc[j+1]);
        if (g >= r && gnext < r) {
            s->prefix |= (base + (unsigned)j) << shift;
            s->r = (int)(r - gnext);
        }
    }
}

__device__ __forceinline__ void load_keys(const SmemT* s, int i4, unsigned kk[4]) {
    const float4 v = reinterpret_cast<const float4*>(s->row)[i4];
    kk[0] = __float_as_uint(v.x) & 0x7fffffffu;
    kk[1] = __float_as_uint(v.y) & 0x7fffffffu;
    kk[2] = __float_as_uint(v.z) & 0x7fffffffu;
    kk[3] = __float_as_uint(v.w) & 0x7fffffffu;
}

__global__ void __launch_bounds__(TPB, 2)
topk_kernel(const float* __restrict__ x, const int* __restrict__ kptr,
            float* __restrict__ out)
{
    extern __shared__ unsigned char smem_raw[];
    SmemT* s = reinterpret_cast<SmemT*>(smem_raw);
    const int tid  = threadIdx.x;
    const int w    = tid >> 5;
    const int lane = tid & 31;
    const size_t rowoff = (size_t)blockIdx.x * COLS;
    const float4* __restrict__ xin  = reinterpret_cast<const float4*>(x + rowoff);
    float4* __restrict__       xout = reinterpret_cast<float4*>(out + rowoff);

    const int k = *kptr;
    if (k >= COLS) {
#pragma unroll
        for (int i = 0; i < V4; i++) xout[i*TPB + tid] = xin[i*TPB + tid];
        return;
    }
    if (k <= 0) {
        float4 z = make_float4(0.f, 0.f, 0.f, 0.f);
#pragma unroll
        for (int i = 0; i < V4; i++) xout[i*TPB + tid] = z;
        return;
    }

    // ---- init ----
    unsigned* hflat = &s->u.hist[0][0];
    for (int i = tid; i < NW * 256; i += TPB) hflat[i] = 0u;
    if (tid == 0) { s->prefix = 0u; s->r = k; s->eqCount = 0; s->candCount = 0; }
    __syncthreads();

    // ---- load gmem -> smem, fused level-0 histogram (digit = key >> 23) ----
    unsigned* hw = s->u.hist[w];
#pragma unroll
    for (int i = 0; i < V4; i++) {
        const int i4 = i * TPB + tid;
        float4 v = xin[i4];
        reinterpret_cast<float4*>(s->row)[i4] = v;
        hist_add(hw, (__float_as_uint(v.x) & 0x7fffffffu) >> 23);
        hist_add(hw, (__float_as_uint(v.y) & 0x7fffffffu) >> 23);
        hist_add(hw, (__float_as_uint(v.z) & 0x7fffffffu) >> 23);
        hist_add(hw, (__float_as_uint(v.w) & 0x7fffffffu) >> 23);
    }
    __syncthreads();

    // ---- level 0: merge + select ----
    if (tid < 256) {
        unsigned t = 0;
#pragma unroll
        for (int ww = 0; ww < NW; ww++) t += s->u.hist[ww][tid];
        s->tot[tid] = t;
    }
    __syncthreads();
    if (tid < 32) select_bin(s, 23);
    __syncthreads();

    // ---- compaction: collect elements in the selected exponent bucket ----
    const unsigned digit0 = s->prefix >> 23;
    const unsigned ltmask = (lane == 31) ? 0x7fffffffu : ((1u << lane) - 1u);
#pragma unroll
    for (int i = 0; i < V4; i++) {
        const int i4 = i * TPB + tid;
        unsigned kk[4]; load_keys(s, i4, kk);
#pragma unroll
        for (int j = 0; j < 4; j++) {
            const bool c = (kk[j] >> 23) == digit0;
            unsigned m = __ballot_sync(0xffffffffu, c);
            if (m) {
                const unsigned leader = __ffs(m) - 1u;
                int base = 0;
                if ((unsigned)lane == leader)
                    base = atomicAdd(&s->candCount, __popc(m));
                base = __shfl_sync(0xffffffffu, base, leader);
                if (c) {
                    int pos = base + __popc(m & ltmask);
                    if (pos < CAP)
                        s->u.cand[pos] =
                            ((unsigned long long)kk[j] << 32) | (unsigned)(i4 * 4 + j);
                }
            }
        }
    }
    __syncthreads();

    const int  cnt      = s->candCount;
    const bool overflow = (cnt > CAP);

    // ---- levels 1..3 refine (8+8+7 bits) ----
#pragma unroll
    for (int lev = 1; lev < 4; lev++) {
        const int      shift = (lev == 1) ? 15 : (lev == 2) ? 7 : 0;
        const int      hi    = (lev == 1) ? 23 : (lev == 2) ? 15 : 7;
        const unsigned mask  = (lev == 3) ? 0x7fu : 0xffu;
        const unsigned pref_hi = s->prefix >> hi;

        if (tid < 256) s->tot[tid] = 0u;
        __syncthreads();

        if (!overflow) {
            const int cntPad = (cnt + TPB - 1) & ~(TPB - 1);
            for (int i = tid; i < cntPad; i += TPB) {
                unsigned d = 0x100u;
                if (i < cnt) {
                    unsigned key = (unsigned)(s->u.cand[i] >> 32);
                    if ((key >> hi) == pref_hi) d = (key >> shift) & mask;
                }
                hist_add_atomic(s->tot, d);
            }
        } else {
#pragma unroll
            for (int i = 0; i < V4; i++) {
                unsigned kk[4]; load_keys(s, i * TPB + tid, kk);
#pragma unroll
                for (int j = 0; j < 4; j++) {
                    unsigned d = ((kk[j] >> hi) == pref_hi) ? ((kk[j] >> shift) & mask)
                                                            : 0x100u;
                    hist_add_atomic(s->tot, d);
                }
            }
        }
        __syncthreads();
        if (tid < 32) select_bin(s, shift);
        __syncthreads();
    }

    const unsigned thr = s->prefix;   // exact |x| bit pattern at the rank boundary
    // s->r = number of elements equal to thr still to keep (>=1)

    // ---- collect indices equal to threshold (lowest-index tie-break) ----
    if (!overflow) {
        for (int i = tid; i < cnt; i += TPB) {
            const unsigned long long rec = s->u.cand[i];
            if ((unsigned)(rec >> 32) == thr) {
                int pos = atomicAdd(&s->eqCount, 1);
                if (pos < EQ_CAP) s->eqIdx[pos] = (int)(unsigned)rec;
            }
        }
    } else {
#pragma unroll
        for (int i = 0; i < V4; i++) {
            const int i4 = i * TPB + tid;
            unsigned kk[4]; load_keys(s, i4, kk);
#pragma unroll
            for (int j = 0; j < 4; j++) {
                if (kk[j] == thr) {
                    int pos = atomicAdd(&s->eqCount, 1);
                    if (pos < EQ_CAP) s->eqIdx[pos] = i4 * 4 + j;
                }
            }
        }
    }
    __syncthreads();
    if (tid == 0) {
        int e = s->eqCount; if (e > EQ_CAP) e = EQ_CAP;
        int m = s->r;       if (m > e) m = e;
        for (int a = 1; a < e; a++) {                 // tiny insertion sort
            int v = s->eqIdx[a]; int b = a - 1;
            while (b >= 0 && s->eqIdx[b] > v) { s->eqIdx[b + 1] = s->eqIdx[b]; b--; }
            s->eqIdx[b + 1] = v;
        }
        s->cutoff = (m > 0) ? s->eqIdx[m - 1] : -1;
    }
    __syncthreads();

    // ---- output pass: smem -> gmem ----
    const int cut = s->cutoff;
#pragma unroll
    for (int i = 0; i < V4; i++) {
        const int i4 = i * TPB + tid;
        const float4 v = reinterpret_cast<const float4*>(s->row)[i4];
        unsigned kk[4];
        kk[0] = __float_as_uint(v.x) & 0x7fffffffu;
        kk[1] = __float_as_uint(v.y) & 0x7fffffffu;
        kk[2] = __float_as_uint(v.z) & 0x7fffffffu;
        kk[3] = __float_as_uint(v.w) & 0x7fffffffu;
        const int e0 = i4 * 4;
        float4 o;
        o.x = (kk[0] > thr || (kk[0] == thr && (e0 + 0) <= cut)) ? v.x : 0.f;
        o.y = (kk[1] > thr || (kk[1] == thr && (e0 + 1) <= cut)) ? v.y : 0.f;
        o.z = (kk[2] > thr || (kk[2] == thr && (e0 + 2) <= cut)) ? v.z : 0.f;
        o.w = (kk[3] > thr || (kk[3] == thr && (e0 + 3) <= cut)) ? v.w : 0.f;
        xout[i4] = o;
    }
}

extern "C" void kernel_launch(void* const* d_in, const int* in_sizes, int n_in,
                              void* d_out, int out_size)
{
    const float* x = (const float*)d_in[0];
    const int*   k = (const int*)d_in[1];
    float* out = (float*)d_out;
    const int rows = in_sizes[0] / COLS;

    cudaFuncSetAttribute(topk_kernel,
                         cudaFuncAttributeMaxDynamicSharedMemorySize,
                         (int)sizeof(SmemT));
    topk_kernel<<<rows, TPB, sizeof(SmemT)>>>(x, k, out);
}